// round 2
// baseline (speedup 1.0000x reference)
#include <cuda_runtime.h>

#define NN 320
#define DD 64

// Precomputed, perm-independent state (static device globals: no allocation).
__device__ float d_Dp[NN*NN];   // pairwise distance ||x_a - x_b||
__device__ float d_Dl[NN*NN];   // Delta = ||x_a + x_b|| - ||x_a - x_b||
__device__ float d_RD[NN];      // row sums of Delta (incl. diagonal)
__device__ float d_rowC[NN];    // per-row sum of Dp over b>a
__device__ float d_sn[NN];      // squared norms
__device__ float d_scal[2];     // [0] = C_Dp = sum_{a<b} Dp, [1] = S1 = sum sn

__device__ __forceinline__ float warpRed(float v){
#pragma unroll
    for (int o = 16; o > 0; o >>= 1) v += __shfl_down_sync(0xffffffffu, v, o);
    return v;
}

// Kernel 1: squared norms
__global__ void k_pre1(const float* __restrict__ x){
    int t = threadIdx.x;
    const float4* r = reinterpret_cast<const float4*>(x + t*DD);
    float s = 0.f;
#pragma unroll
    for (int i = 0; i < DD/4; i++){ float4 v = r[i]; s += v.x*v.x + v.y*v.y + v.z*v.z + v.w*v.w; }
    d_sn[t] = s;
}

// Kernel 2: Dp, Delta, row sums. One block per row a, thread = column b.
__global__ void __launch_bounds__(NN) k_pre2(const float* __restrict__ x){
    __shared__ float xa[DD];
    __shared__ float red[2][10];
    int a = blockIdx.x, b = threadIdx.x;
    if (b < DD) xa[b] = x[a*DD + b];
    __syncthreads();
    const float4* xb = reinterpret_cast<const float4*>(x + b*DD);
    float g = 0.f;
#pragma unroll
    for (int i = 0; i < DD/4; i++){
        float4 v = xb[i];
        g += xa[4*i]*v.x + xa[4*i+1]*v.y + xa[4*i+2]*v.z + xa[4*i+3]*v.w;
    }
    float sa = d_sn[a], sb = d_sn[b];
    float dp = sqrtf(fmaxf(sa + sb - 2.f*g, 0.f));
    float dm = sqrtf(fmaxf(sa + sb + 2.f*g, 0.f));
    float dl = dm - dp;
    d_Dp[a*NN + b] = dp;
    d_Dl[a*NN + b] = dl;
    int w = b >> 5, l = b & 31;
    float v0 = warpRed(dl);
    float v1 = warpRed(b > a ? dp : 0.f);
    if (l == 0){ red[0][w] = v0; red[1][w] = v1; }
    __syncthreads();
    if (b == 0){
        float s0 = 0.f, s1 = 0.f;
#pragma unroll
        for (int i = 0; i < 10; i++){ s0 += red[0][i]; s1 += red[1][i]; }
        d_RD[a]   = s0;
        d_rowC[a] = s1;
    }
}

// Kernel 3: scalar reductions (deterministic, no atomics)
__global__ void k_pre3(){
    __shared__ float red[2][10];
    int t = threadIdx.x, w = t >> 5, l = t & 31;
    float v0 = warpRed(d_rowC[t]);
    float v1 = warpRed(d_sn[t]);
    if (l == 0){ red[0][w] = v0; red[1][w] = v1; }
    __syncthreads();
    if (t == 0){
        float s0 = 0.f, s1 = 0.f;
#pragma unroll
        for (int i = 0; i < 10; i++){ s0 += red[0][i]; s1 += red[1][i]; }
        d_scal[0] = s0; d_scal[1] = s1;
    }
}

// Kernel 4: one block per dataset (block 0 = identity, block p>=1 = perms[p-1]).
__global__ void __launch_bounds__(NN) k_main(const float* __restrict__ x,
                                             const int* __restrict__ ptype,
                                             const int* __restrict__ perms,
                                             float* __restrict__ out){
    __shared__ float beta[NN], chi[NN];
    __shared__ int   Bl[NN], Cl[NN];
    __shared__ int   offB[10], offC[10], cnt[2];
    __shared__ float zp[NN];
    __shared__ float red[5][10];

    int t = threadIdx.x, p = blockIdx.x;
    int w = t >> 5, l = t & 31;

    beta[t] = 0.f; chi[t] = 0.f;
    __syncthreads();

    int a  = (p == 0) ? t : perms[(p-1)*NN + t];
    int fn = (ptype[t] == 0);
    int fa = (ptype[a] == 0);
    int u  = (a != t) && fn && fa;          // this position's row is negated
    if (fn) chi[a]  = 1.f;                  // image of a fermion position
    if (u)  beta[a] = 1.f;                  // image of a negated position

    // Deterministic warp-ballot compaction into index lists
    unsigned ballB = __ballot_sync(0xffffffffu, u);
    unsigned ballC = __ballot_sync(0xffffffffu, fn);
    if (l == 0){ offB[w] = __popc(ballB); offC[w] = __popc(ballC); }
    __syncthreads();
    if (t == 0){
        int sB = 0, sC = 0;
#pragma unroll
        for (int i = 0; i < 10; i++){
            int bb = offB[i]; offB[i] = sB; sB += bb;
            int cc = offC[i]; offC[i] = sC; sC += cc;
        }
        cnt[0] = sB; cnt[1] = sC;
    }
    __syncthreads();
    unsigned lt = (1u << l) - 1u;
    if (u)  Bl[offB[w] + __popc(ballB & lt)] = a;
    if (fn) Cl[offC[w] + __popc(ballC & lt)] = a;
    __syncthreads();
    int Bc = cnt[0], Cc = cnt[1];

    // z = sum_a (1 - 2*beta_a) x_a ; 5 groups of 64 threads, group gg covers rows [64gg,64gg+63]
    int d = t & 63, gg = t >> 6;
    float zacc = 0.f;
    const float* xg = x + (gg*64)*DD + d;
#pragma unroll 4
    for (int k = 0; k < 64; k++)
        zacc += (1.f - 2.f*beta[gg*64 + k]) * xg[k*DD];
    zp[t] = zacc;
    __syncthreads();
    float z2p = 0.f;
    if (t < 64){
        float z = zp[t] + zp[64+t] + zp[128+t] + zp[192+t] + zp[256+t];
        z2p = z*z;
    }

    // Column sums of gathered rows (coalesced: thread t = column t)
    float colB = 0.f, colX = 0.f;
#pragma unroll 4
    for (int i = 0; i < Bc; i++) colB += d_Dl[Bl[i]*NN + t];
#pragma unroll 4
    for (int i = 0; i < Cc; i++) colX += d_Dp[Cl[i]*NN + t];

    float myb = beta[t], myc = chi[t];
    float vBB  = myb * colB;                       // beta^T Delta beta
    float vBX  = myc * colB;                       // beta^T Delta chi
    float vXX  = myc * colX;                       // chi^T Dp chi
    float vLin = (t < Bc) ? d_RD[Bl[t]] : 0.f;     // beta^T RDelta

    float r0 = warpRed(vBB), r1 = warpRed(vBX), r2 = warpRed(vXX),
          r3 = warpRed(vLin), r4 = warpRed(z2p);
    if (l == 0){ red[0][w]=r0; red[1][w]=r1; red[2][w]=r2; red[3][w]=r3; red[4][w]=r4; }
    __syncthreads();
    if (t == 0){
        float BB=0.f, BX=0.f, XX=0.f, LIN=0.f, Z2=0.f;
#pragma unroll
        for (int i = 0; i < 10; i++){
            BB += red[0][i]; BX += red[1][i]; XX += red[2][i];
            LIN += red[3][i]; Z2 += red[4][i];
        }
        const float M = 51040.f;                    // 320*319/2
        float Sv  = d_scal[0] + LIN + BB - 2.f*BX - XX;
        float Sv2 = 320.f * d_scal[1] - Z2;
        out[p] = (Sv2 - Sv*Sv/M) / (M - 1.f);
    }
}

extern "C" void kernel_launch(void* const* d_in, const int* in_sizes, int n_in,
                              void* d_out, int out_size){
    const float* data  = (const float*)d_in[0];
    const int*   ptype = (const int*)d_in[3];
    const int*   perms = (const int*)d_in[4];
    float* out = (float*)d_out;
    k_pre1<<<1, NN>>>(data);
    k_pre2<<<NN, NN>>>(data);
    k_pre3<<<1, NN>>>();
    k_main<<<1001, NN>>>(data, ptype, perms, out);
}